// round 1
// baseline (speedup 1.0000x reference)
#include <cuda_runtime.h>
#include <math.h>
#include <float.h>

#define TT 256
#define BB 32
#define CC 64
#define BEAM 16
#define TOPK 4
#define NEGV (-1e9f)

// log-softmax scratch: [T, B, C] (2 MB, allowed as __device__ global)
__device__ float g_lp[TT * BB * CC];

__device__ __forceinline__ float laexp(float a, float b) {
    // matches jnp.logaddexp for finite inputs
    return fmaxf(a, b) + log1pf(expf(-fabsf(a - b)));
}

// ---------------------------------------------------------------------------
// Pre-pass: log_softmax over C for every (t, b) row. 8 warps/block, 1 row/warp.
// ---------------------------------------------------------------------------
__global__ void logsoftmax_kernel(const float* __restrict__ data) {
    int row  = blockIdx.x * 8 + (threadIdx.x >> 5);
    int lane = threadIdx.x & 31;
    if (row >= TT * BB) return;
    const float* x = data + row * CC;
    float v0 = x[lane], v1 = x[lane + 32];
    float m = fmaxf(v0, v1);
    #pragma unroll
    for (int o = 16; o; o >>= 1) m = fmaxf(m, __shfl_xor_sync(0xffffffffu, m, o));
    float s = expf(v0 - m) + expf(v1 - m);
    #pragma unroll
    for (int o = 16; o; o >>= 1) s += __shfl_xor_sync(0xffffffffu, s, o);
    float ls = logf(s);
    g_lp[row * CC + lane]      = (v0 - m) - ls;
    g_lp[row * CC + lane + 32] = (v1 - m) - ls;
}

// ---------------------------------------------------------------------------
// Main: one block per batch element; 256 threads; serial loop over T frames.
// ---------------------------------------------------------------------------
__global__ __launch_bounds__(256) void ctc_beam_kernel(
    const int* __restrict__ dlen, float* __restrict__ out)
{
    __shared__ float lp[CC];
    __shared__ float p_b[BEAM], p_nb[BEAM], tot[BEAM];
    __shared__ unsigned h1s[BEAM], h2s[BEAM];
    __shared__ int lens[BEAM], lastc[BEAM], curn[BEAM], acts[BEAM];
    __shared__ float stay_pb[BEAM], stay_pnb[BEAM];
    __shared__ float scores[BEAM + BEAM * CC];       // 16 stays + 1024 extends
    __shared__ float selv[BEAM];
    __shared__ int   seli[BEAM];
    __shared__ int   nodes[TT * BEAM];               // backpointer arena (16 KB)
    __shared__ int   order_s[TOPK];

    int b    = blockIdx.x;
    int tid  = threadIdx.x;
    int lane = tid & 31;
    int wid  = tid >> 5;

    if (tid < BEAM) {
        p_b[tid]  = (tid == 0) ? 0.0f : NEGV;
        p_nb[tid] = NEGV;
        h1s[tid] = 0u;  h2s[tid] = 0u;
        lens[tid] = 0;  lastc[tid] = -1;  curn[tid] = -1;
        acts[tid] = (tid == 0) ? 1 : 0;
    }
    int length = dlen[b];
    if (length > TT) length = TT;
    __syncthreads();

    for (int t = 0; t < length; ++t) {
        // ---- load log-probs + per-beam totals --------------------------------
        if (tid < CC) lp[tid] = g_lp[(t * BB + b) * CC + tid];
        if (tid >= 64 && tid < 64 + BEAM) {
            int i = tid - 64;
            tot[i] = laexp(p_b[i], p_nb[i]);
        }
        __syncthreads();

        // ---- stay candidates + extend scores ---------------------------------
        if (tid < BEAM) {
            stay_pb[tid]  = tot[tid] + lp[0];
            stay_pnb[tid] = (lens[tid] > 0) ? (p_nb[tid] + lp[lastc[tid]]) : NEGV;
        }
        #pragma unroll
        for (int q = 0; q < 4; ++q) {
            int e = tid + q * 256;
            int i = e >> 6, c = e & 63;
            float v;
            if (c == 0 || !acts[i]) v = NEGV;
            else {
                float base = (c == lastc[i]) ? p_b[i] : tot[i];
                v = base + lp[c];
            }
            scores[BEAM + e] = v;
        }
        __syncthreads();

        // ---- duplicate-prefix merge: warp w handles beams j=2w, 2w+1 ---------
        #pragma unroll
        for (int jj = 0; jj < 2; ++jj) {
            int j = wid * 2 + jj;
            int aj = acts[j];
            unsigned hj1 = h1s[j], hj2 = h2s[j];
            float m = NEGV;
            for (int e = lane; e < BEAM * CC; e += 32) {
                int i = e >> 6; unsigned cc = (unsigned)(e & 63) + 1u;
                bool mt = aj && (h1s[i] * 1000003u + cc) == hj1
                             && (h2s[i] * 69069u   + cc) == hj2;
                float v = mt ? scores[BEAM + e] : NEGV;
                m = fmaxf(m, v);
            }
            #pragma unroll
            for (int o = 16; o; o >>= 1) m = fmaxf(m, __shfl_xor_sync(0xffffffffu, m, o));
            float s = 0.0f;
            for (int e = lane; e < BEAM * CC; e += 32) {
                int i = e >> 6; unsigned cc = (unsigned)(e & 63) + 1u;
                bool mt = aj && (h1s[i] * 1000003u + cc) == hj1
                             && (h2s[i] * 69069u   + cc) == hj2;
                float v = mt ? scores[BEAM + e] : NEGV;
                s += expf(v - m);            // NEG fillers underflow to 0 exactly as in JAX
            }
            #pragma unroll
            for (int o = 16; o; o >>= 1) s += __shfl_xor_sync(0xffffffffu, s, o);
            if (lane == 0) {
                float merged = m + logf(s);
                stay_pnb[j] = laexp(stay_pnb[j], merged);
            }
        }
        __syncthreads();

        // ---- mask merged extends; finalize stay totals ------------------------
        #pragma unroll
        for (int q = 0; q < 4; ++q) {
            int e = tid + q * 256;
            int i = e >> 6; unsigned cc = (unsigned)(e & 63) + 1u;
            unsigned c1 = h1s[i] * 1000003u + cc;
            unsigned c2 = h2s[i] * 69069u   + cc;
            bool any = false;
            #pragma unroll
            for (int j = 0; j < BEAM; ++j)
                any = any || (acts[j] && c1 == h1s[j] && c2 == h2s[j]);
            if (any) scores[BEAM + e] = NEGV;
        }
        if (tid < BEAM) scores[tid] = laexp(stay_pb[tid], stay_pnb[tid]);
        __syncthreads();

        // ---- top-16 of 1040, stable (value desc, index asc) — warp 0 ----------
        if (wid == 0) {
            for (int k = 0; k < BEAM; ++k) {
                float bv = -FLT_MAX; int bi = 0x7fffffff;
                for (int e = lane; e < BEAM + BEAM * CC; e += 32) {
                    float v = scores[e];
                    if (v > bv || (v == bv && e < bi)) { bv = v; bi = e; }
                }
                #pragma unroll
                for (int o = 16; o; o >>= 1) {
                    float ov = __shfl_xor_sync(0xffffffffu, bv, o);
                    int   oi = __shfl_xor_sync(0xffffffffu, bi, o);
                    if (ov > bv || (ov == bv && oi < bi)) { bv = ov; bi = oi; }
                }
                if (lane == 0) { selv[k] = bv; seli[k] = bi; scores[bi] = -FLT_MAX; }
                __syncwarp();
            }
        }
        __syncthreads();

        // ---- build new beam state (stage reads, then commit) ------------------
        float npb = 0.f, npnb = 0.f; unsigned nh1 = 0u, nh2 = 0u;
        int nlen = 0, nlast = 0, ncur = 0, nact = 0, nodeval = 0;
        bool isext = false;
        if (tid < BEAM) {
            int idx = seli[tid]; float val = selv[tid];
            bool st = idx < BEAM;
            int parent = st ? idx : ((idx - BEAM) >> 6);
            int cnew   = st ? 0   : ((idx - BEAM) & 63);
            npb  = st ? stay_pb[parent]  : NEGV;
            npnb = st ? stay_pnb[parent] : val;
            unsigned cc = (unsigned)cnew + 1u;
            nh1 = st ? h1s[parent] : (h1s[parent] * 1000003u + cc);
            nh2 = st ? h2s[parent] : (h2s[parent] * 69069u   + cc);
            nlen  = lens[parent] + (st ? 0 : 1);
            nlast = st ? lastc[parent] : cnew;
            int pcur = curn[parent];
            ncur  = st ? pcur : (t * BEAM + tid);
            nact  = (val > -5e8f) ? 1 : 0;    // vals > NEG/2
            isext = !st;
            nodeval = ((pcur + 1) << 6) | cnew;
        }
        __syncthreads();
        if (tid < BEAM) {
            p_b[tid] = npb;  p_nb[tid] = npnb;
            h1s[tid] = nh1;  h2s[tid] = nh2;
            lens[tid] = nlen; lastc[tid] = nlast; curn[tid] = ncur; acts[tid] = nact;
            if (isext) nodes[t * BEAM + tid] = nodeval;
        }
        __syncthreads();
    }

    // ---- final selection of top-4 beams + output ------------------------------
    if (tid < BEAM) tot[tid] = laexp(p_b[tid], p_nb[tid]);
    // labels region default: -1
    for (int e = tid; e < TOPK * TT; e += 256)
        out[2 * BB * TOPK + b * TOPK * TT + e] = -1.0f;
    __syncthreads();

    if (tid == 0) {
        unsigned used = 0u;
        for (int k = 0; k < TOPK; ++k) {
            float bv = -FLT_MAX; int bi = 0;
            for (int i = 0; i < BEAM; ++i) {
                if ((used >> i) & 1u) continue;
                if (tot[i] > bv) { bv = tot[i]; bi = i; }   // stable: first-seen on ties
            }
            used |= 1u << bi;
            order_s[k] = bi;
            out[b * TOPK + k]             = -bv;            // probs
            out[BB * TOPK + b * TOPK + k] = (float)lens[bi]; // lengths
        }
    }
    __syncthreads();

    if (tid < TOPK) {
        int bm = order_s[tid];
        int id = curn[bm];
        float* lbl = out + 2 * BB * TOPK + (b * TOPK + tid) * TT;
        for (int pos = lens[bm] - 1; pos >= 0; --pos) {
            int pk = nodes[id];
            lbl[pos] = (float)(pk & 63);
            id = (pk >> 6) - 1;
        }
    }
}

extern "C" void kernel_launch(void* const* d_in, const int* in_sizes, int n_in,
                              void* d_out, int out_size)
{
    const float* data = (const float*)d_in[0];
    const int*   dlen = (const int*)d_in[1];
    float*       out  = (float*)d_out;

    logsoftmax_kernel<<<(TT * BB) / 8, 256>>>(data);
    ctc_beam_kernel<<<BB, 256>>>(dlen, out);
}

// round 2
// speedup vs baseline: 2.9671x; 2.9671x over previous
#include <cuda_runtime.h>
#include <math.h>
#include <float.h>

#define TT 256
#define BB 32
#define CC 64
#define BEAM 16
#define TOPK 4
#define NEGV (-1e9f)

// log-softmax scratch: [T, B, C]
__device__ float g_lp[TT * BB * CC];

__device__ __forceinline__ float laexp(float a, float b) {
    return fmaxf(a, b) + log1pf(expf(-fabsf(a - b)));
}
// monotone float->u32 mapping (total order matching float compare)
__device__ __forceinline__ unsigned f2ord(float v) {
    unsigned u = __float_as_uint(v);
    return u ^ (unsigned)(((int)u >> 31) | 0x80000000);
}
__device__ __forceinline__ float ord2f(unsigned o) {
    unsigned u = (o & 0x80000000u) ? (o ^ 0x80000000u) : ~o;
    return __uint_as_float(u);
}

// ---------------------------------------------------------------------------
// Pre-pass: log_softmax over C for every (t, b) row.
// ---------------------------------------------------------------------------
__global__ void logsoftmax_kernel(const float* __restrict__ data) {
    int row  = blockIdx.x * 8 + (threadIdx.x >> 5);
    int lane = threadIdx.x & 31;
    if (row >= TT * BB) return;
    const float* x = data + row * CC;
    float v0 = x[lane], v1 = x[lane + 32];
    float m = fmaxf(v0, v1);
    #pragma unroll
    for (int o = 16; o; o >>= 1) m = fmaxf(m, __shfl_xor_sync(0xffffffffu, m, o));
    float s = expf(v0 - m) + expf(v1 - m);
    #pragma unroll
    for (int o = 16; o; o >>= 1) s += __shfl_xor_sync(0xffffffffu, s, o);
    float ls = logf(s);
    g_lp[row * CC + lane]      = (v0 - m) - ls;
    g_lp[row * CC + lane + 32] = (v1 - m) - ls;
}

// ---------------------------------------------------------------------------
// Main: one block per batch element; 256 threads; serial loop over T frames.
// ---------------------------------------------------------------------------
__global__ __launch_bounds__(256) void ctc_beam_kernel(
    const int* __restrict__ dlen, float* __restrict__ out)
{
    __shared__ float p_b[BEAM], p_nb[BEAM], tot[BEAM];
    __shared__ float stay_pb_s[BEAM], stay_pnb_s[BEAM];
    __shared__ unsigned long long hcomb[BEAM];      // (h1<<32)|h2 per beam
    __shared__ unsigned actmask_s;                  // bit j = acts[j]
    __shared__ int lens[BEAM], lastc[BEAM], curn[BEAM];
    __shared__ unsigned long long kbuf[BEAM + BEAM * CC];  // 1040 sortable keys
    __shared__ float selv[BEAM];
    __shared__ int   seli[BEAM];
    __shared__ int   mcount;
    __shared__ float mval[32];
    __shared__ int   mmask[32];
    __shared__ int   nodes[TT * BEAM];              // backpointer arena
    __shared__ int   order_s[TOPK];

    int b    = blockIdx.x;
    int tid  = threadIdx.x;
    int lane = tid & 31;
    int wid  = tid >> 5;

    if (tid < BEAM) {
        float pb = (tid == 0) ? 0.0f : NEGV;
        p_b[tid]  = pb;
        p_nb[tid] = NEGV;
        tot[tid]  = laexp(pb, NEGV);
        hcomb[tid] = 0ull;
        lens[tid] = 0;  lastc[tid] = -1;  curn[tid] = -1;
    }
    if (tid == 0) { mcount = 0; actmask_s = 1u; }

    int length = dlen[b];
    if (length > TT) length = TT;
    int myc = tid & 63;
    // per-thread lp prefetch for frame 0
    float lpc = g_lp[b * CC + myc];
    // warp-0 per-beam lp prefetches for frame 0 (lastc = -1 -> index 0)
    float lp0 = 0.0f, lpl = 0.0f;
    if (tid < BEAM) { lp0 = g_lp[b * CC]; lpl = lp0; }
    __syncthreads();

    for (int t = 0; t < length; ++t) {
        // ==== phase B (all 256 threads): ext scores, hashes, match list ======
        unsigned actm = actmask_s;
        for (int q = 0; q < 4; ++q) {
            int e = q * 256 + tid;
            int i = e >> 6;
            unsigned long long hci = hcomb[i];
            unsigned h1i = (unsigned)(hci >> 32), h2i = (unsigned)hci;
            int ai = (actm >> i) & 1;
            float base = (myc == lastc[i]) ? p_b[i] : tot[i];
            float ev = (myc == 0 || !ai) ? NEGV : (base + lpc);
            unsigned cc1 = (unsigned)myc + 1u;
            unsigned ch1 = h1i * 1000003u + cc1;
            unsigned ch2 = h2i * 69069u   + cc1;
            unsigned long long myhc = ((unsigned long long)ch1 << 32) | ch2;
            unsigned mk = 0;
            #pragma unroll
            for (int j = 0; j < BEAM; ++j)
                mk |= (hcomb[j] == myhc) ? (1u << j) : 0u;
            mk &= actm;
            if (mk) {
                int pos = atomicAdd(&mcount, 1);
                if (pos < 32) { mval[pos] = ev; mmask[pos] = (int)mk; }
            }
            float sv = mk ? NEGV : ev;
            kbuf[BEAM + e] = ((unsigned long long)f2ord(sv) << 32)
                           | (unsigned)(2047 - (BEAM + e));
        }
        __syncthreads();   // S2: kbuf + match list visible to warp 0

        if (wid == 0) {
            // ==== phase C1: merge + stay candidates (lanes 0..15) ============
            if (lane < BEAM) {
                int j = lane;
                float spb = tot[j] + lp0;
                float spnb = (lens[j] > 0) ? (p_nb[j] + lpl) : NEGV;
                int n = mcount; if (n > 32) n = 32;
                float mx = NEGV; int k = 0;
                for (int l = 0; l < n; ++l)
                    if ((mmask[l] >> j) & 1) { mx = fmaxf(mx, mval[l]); k++; }
                float s = 0.0f;
                for (int l = 0; l < n; ++l)
                    if ((mmask[l] >> j) & 1) s += expf(mval[l] - mx);
                s += (float)(1024 - k) * expf(NEGV - mx);
                float merged = mx + logf(s);
                spnb = laexp(spnb, merged);
                stay_pb_s[j]  = spb;
                stay_pnb_s[j] = spnb;
                float st = laexp(spb, spnb);
                kbuf[j] = ((unsigned long long)f2ord(st) << 32)
                        | (unsigned)(2047 - j);
            }
            __syncwarp();

            // ==== phase C2: top-16 of 1040 via register keys + redux =========
            unsigned long long kk[33];
            #pragma unroll
            for (int m = 0; m < 33; ++m) {
                int e = m * 32 + lane;
                kk[m] = (e < BEAM + BEAM * CC) ? kbuf[e] : 0ull;
            }
            unsigned long long lm = 0ull;
            #pragma unroll
            for (int m = 0; m < 33; ++m) if (kk[m] > lm) lm = kk[m];

            for (int k2 = 0; k2 < BEAM; ++k2) {
                unsigned up = (unsigned)(lm >> 32);
                unsigned um = __reduce_max_sync(0xffffffffu, up);
                unsigned lo = (up == um) ? (unsigned)lm : 0u;
                unsigned lw = __reduce_max_sync(0xffffffffu, lo);
                bool win = (up == um) && ((unsigned)lm == lw);
                unsigned bal = __ballot_sync(0xffffffffu, win);
                int wl = __ffs((int)bal) - 1;
                if (lane == wl) {
                    seli[k2] = 2047 - (int)lw;
                    selv[k2] = ord2f(um);
                    unsigned long long wkey =
                        ((unsigned long long)um << 32) | lw;
                    #pragma unroll
                    for (int m = 0; m < 33; ++m)
                        if (kk[m] == wkey) kk[m] = 0ull;
                    unsigned long long nl = 0ull;
                    #pragma unroll
                    for (int m = 0; m < 33; ++m) if (kk[m] > nl) nl = kk[m];
                    lm = nl;
                }
                __syncwarp();
            }

            // ==== phase C3: commit new beam state (lanes 0..15) ==============
            int nact_flag = 0;
            if (lane < BEAM) {
                int j = lane;
                int idx = seli[j]; float val = selv[j];
                bool st = idx < BEAM;
                int parent = st ? idx : ((idx - BEAM) >> 6);
                int cnew   = st ? 0   : ((idx - BEAM) & 63);
                float npb  = st ? stay_pb_s[parent]  : NEGV;
                float npnb = st ? stay_pnb_s[parent] : val;
                unsigned long long hp = hcomb[parent];
                unsigned ph1 = (unsigned)(hp >> 32), ph2 = (unsigned)hp;
                unsigned cc1 = (unsigned)cnew + 1u;
                unsigned nh1 = st ? ph1 : (ph1 * 1000003u + cc1);
                unsigned nh2 = st ? ph2 : (ph2 * 69069u   + cc1);
                int nlen  = lens[parent] + (st ? 0 : 1);
                int nlast = st ? lastc[parent] : cnew;
                int pcur  = curn[parent];
                int ncur  = st ? pcur : (t * BEAM + j);
                nact_flag = (val > -5e8f) ? 1 : 0;
                __syncwarp(0x0000ffffu);   // reads done before writes
                p_b[j] = npb;  p_nb[j] = npnb;
                hcomb[j] = ((unsigned long long)nh1 << 32) | nh2;
                lens[j] = nlen; lastc[j] = nlast; curn[j] = ncur;
                tot[j] = laexp(npb, npnb);
                if (!st) nodes[t * BEAM + j] = ((pcur + 1) << 6) | cnew;
                // prefetch per-beam lp values for next frame
                int nr = t + 1; if (nr > TT - 1) nr = TT - 1;
                const float* lprow = g_lp + (nr * BB + b) * CC;
                lp0 = lprow[0];
                lpl = lprow[nlast < 0 ? 0 : nlast];
            }
            {   // publish activity bitmask, reset list counter
                unsigned bal = __ballot_sync(0xffffffffu, nact_flag);
                if (lane == 0) { actmask_s = bal & 0xffffu; mcount = 0; }
            }
        }
        // all threads: prefetch their lp for next frame
        {
            int nr = t + 1; if (nr > TT - 1) nr = TT - 1;
            lpc = g_lp[(nr * BB + b) * CC + myc];
        }
        __syncthreads();   // S3: new state published
    }

    // ==== final top-4 + outputs ==============================================
    for (int e = tid; e < TOPK * TT; e += 256)
        out[2 * BB * TOPK + b * TOPK * TT + e] = -1.0f;
    __syncthreads();

    if (tid == 0) {
        unsigned used = 0u;
        for (int k = 0; k < TOPK; ++k) {
            float bv = -FLT_MAX; int bi = 0;
            for (int i = 0; i < BEAM; ++i) {
                if ((used >> i) & 1u) continue;
                if (tot[i] > bv) { bv = tot[i]; bi = i; }  // stable ties
            }
            used |= 1u << bi;
            order_s[k] = bi;
            out[b * TOPK + k]             = -bv;
            out[BB * TOPK + b * TOPK + k] = (float)lens[bi];
        }
    }
    __syncthreads();

    if (tid < TOPK) {
        int bm = order_s[tid];
        int id = curn[bm];
        float* lbl = out + 2 * BB * TOPK + (b * TOPK + tid) * TT;
        for (int pos = lens[bm] - 1; pos >= 0; --pos) {
            int pk = nodes[id];
            lbl[pos] = (float)(pk & 63);
            id = (pk >> 6) - 1;
        }
    }
}

extern "C" void kernel_launch(void* const* d_in, const int* in_sizes, int n_in,
                              void* d_out, int out_size)
{
    const float* data = (const float*)d_in[0];
    const int*   dlen = (const int*)d_in[1];
    float*       out  = (float*)d_out;

    logsoftmax_kernel<<<(TT * BB) / 8, 256>>>(data);
    ctc_beam_kernel<<<BB, 256>>>(dlen, out);
}

// round 3
// speedup vs baseline: 3.7357x; 1.2590x over previous
#include <cuda_runtime.h>
#include <math.h>
#include <float.h>

#define TT 256
#define BB 32
#define CC 64
#define BEAM 16
#define TOPK 4
#define NEGV (-1e9f)

typedef unsigned long long u64;

// log-softmax scratch: [T, B, C]
__device__ float g_lp[TT * BB * CC];

__device__ __forceinline__ float laexp(float a, float b) {
    return fmaxf(a, b) + log1pf(expf(-fabsf(a - b)));
}
// monotone float<->u32 order mapping
__device__ __forceinline__ unsigned f2ord(float v) {
    unsigned u = __float_as_uint(v);
    return u ^ (unsigned)(((int)u >> 31) | 0x80000000);
}
__device__ __forceinline__ float ord2f(unsigned o) {
    unsigned u = (o & 0x80000000u) ? (o ^ 0x80000000u) : ~o;
    return __uint_as_float(u);
}

// ---------------------------------------------------------------------------
__global__ void logsoftmax_kernel(const float* __restrict__ data) {
    int row  = blockIdx.x * 8 + (threadIdx.x >> 5);
    int lane = threadIdx.x & 31;
    if (row >= TT * BB) return;
    const float* x = data + row * CC;
    float v0 = x[lane], v1 = x[lane + 32];
    float m = fmaxf(v0, v1);
    #pragma unroll
    for (int o = 16; o; o >>= 1) m = fmaxf(m, __shfl_xor_sync(0xffffffffu, m, o));
    float s = expf(v0 - m) + expf(v1 - m);
    #pragma unroll
    for (int o = 16; o; o >>= 1) s += __shfl_xor_sync(0xffffffffu, s, o);
    float ls = logf(s);
    g_lp[row * CC + lane]      = (v0 - m) - ls;
    g_lp[row * CC + lane + 32] = (v1 - m) - ls;
}

// ---------------------------------------------------------------------------
// One warp per batch element. All state in shared + registers, no block syncs.
// ---------------------------------------------------------------------------
__global__ __launch_bounds__(32) void ctc_beam_kernel(
    const int* __restrict__ dlen, float* __restrict__ out)
{
    __shared__ float p_b[BEAM], p_nb[BEAM], tot[BEAM];
    __shared__ float stay_pb[BEAM], stay_pnb[BEAM];
    __shared__ u64   hcomb[BEAM], pphash[BEAM], cmask[BEAM];
    __shared__ int   lens[BEAM], lastc[BEAM], curn[BEAM];
    __shared__ float lp_s[CC];
    __shared__ float selv[BEAM];
    __shared__ int   seli[BEAM];
    __shared__ int   nodes[TT * BEAM];
    __shared__ int   order_s[TOPK];

    const unsigned FULL = 0xffffffffu;
    int b = blockIdx.x;
    int lane = threadIdx.x;

    if (lane < BEAM) {
        float pb = (lane == 0) ? 0.0f : NEGV;
        p_b[lane] = pb; p_nb[lane] = NEGV; tot[lane] = laexp(pb, NEGV);
        hcomb[lane] = 0ull; pphash[lane] = 0ull; cmask[lane] = 0ull;
        lens[lane] = 0; lastc[lane] = -1; curn[lane] = -1;
    }
    unsigned actm = 1u;
    int length = dlen[b]; if (length > TT) length = TT;

    // prefetch lp row 0 into registers
    float lpr0 = g_lp[b * CC + lane];
    float lpr1 = g_lp[b * CC + lane + 32];
    __syncwarp();

    for (int t = 0; t < length; ++t) {
        lp_s[lane] = lpr0; lp_s[lane + 32] = lpr1;
        __syncwarp();

        // ==== phase A: merge (lanes 0-15) | extend char-masks (lanes 16-31) ==
        float spb = NEGV, spnb = NEGV;
        if (lane < BEAM) {
            int j = lane;
            int aj = (actm >> j) & 1;
            int lenj = lens[j];
            int lj = lastc[j];
            int ljs = lj < 0 ? 0 : lj;
            u64 pp = pphash[j];
            spb  = tot[j] + lp_s[0];
            spnb = (lenj > 0) ? (p_nb[j] + lp_s[ljs]) : NEGV;
            bool validj = aj && (lenj > 0);
            float mx = NEGV; int cnt = 0;
            if (validj) {
                float lplj = lp_s[ljs];
                #pragma unroll
                for (int i = 0; i < BEAM; ++i) {
                    if (hcomb[i] == pp) {
                        cnt++;
                        float ev = NEGV;
                        if ((actm >> i) & 1)
                            ev = ((lj == lastc[i]) ? p_b[i] : tot[i]) + lplj;
                        mx = fmaxf(mx, ev);
                    }
                }
            }
            float s = 0.0f;
            if (validj && cnt) {
                float lplj = lp_s[ljs];
                #pragma unroll
                for (int i = 0; i < BEAM; ++i) {
                    if (hcomb[i] == pp) {
                        float ev = NEGV;
                        if ((actm >> i) & 1)
                            ev = ((lj == lastc[i]) ? p_b[i] : tot[i]) + lplj;
                        s += expf(ev - mx);
                    }
                }
            }
            s += (float)(1024 - cnt) * expf(NEGV - mx);
            float merged = mx + logf(s);
            spnb = laexp(spnb, merged);
            stay_pb[j] = spb; stay_pnb[j] = spnb;
        } else {
            int i = lane - BEAM;
            u64 hci = hcomb[i];
            u64 cm = 0ull;
            #pragma unroll
            for (int j = 0; j < BEAM; ++j) {
                bool ok = ((actm >> j) & 1) && (lens[j] > 0) && (pphash[j] == hci);
                if (ok) cm |= 1ull << lastc[j];
            }
            cmask[i] = cm;
        }
        __syncwarp();

        // ==== phase B: build 1040 sortable keys in registers (33/lane) =======
        u64 kk[33];
        if (lane < BEAM) {
            float stv = laexp(spb, spnb);
            kk[0] = ((u64)f2ord(stv) << 32) | (unsigned)(2047 - lane);
        } else {
            int x = lane - BEAM;          // entry e=lane -> extend (0, x)
            int c = x;                    // i = 0
            int ai = actm & 1;
            int msk = (int)((cmask[0] >> c) & 1ull);
            float base = (c == lastc[0]) ? p_b[0] : tot[0];
            float v = (c == 0 || !ai || msk) ? NEGV : (base + lp_s[c]);
            kk[0] = ((u64)f2ord(v) << 32) | (unsigned)(2047 - lane);
        }
        #pragma unroll
        for (int m = 1; m < 33; ++m) {
            int e = m * 32 + lane;
            if (e < BEAM + BEAM * CC) {
                int x = e - BEAM;
                int i = x >> 6, c = x & 63;
                int ai = (actm >> i) & 1;
                int msk = (int)((cmask[i] >> c) & 1ull);
                float base = (c == lastc[i]) ? p_b[i] : tot[i];
                float v = (c == 0 || !ai || msk) ? NEGV : (base + lp_s[c]);
                kk[m] = ((u64)f2ord(v) << 32) | (unsigned)(2047 - e);
            } else kk[m] = 0ull;
        }

        // prefetch next lp row (latency hidden behind selection)
        {
            int nr = t + 1; if (nr > TT - 1) nr = TT - 1;
            lpr0 = g_lp[(nr * BB + b) * CC + lane];
            lpr1 = g_lp[(nr * BB + b) * CC + lane + 32];
        }

        // ==== phase C: top-16 of 1040 via redux passes ========================
        u64 gm[6];
        #pragma unroll
        for (int g = 0; g < 6; ++g) {
            int base = g * 6;
            u64 mxk = kk[base];
            #pragma unroll
            for (int r = 1; r < 6; ++r) {
                int idx = base + r;
                if (idx < 33 && kk[idx] > mxk) mxk = kk[idx];
            }
            gm[g] = mxk;
        }
        u64 lm = gm[0];
        #pragma unroll
        for (int g = 1; g < 6; ++g) if (gm[g] > lm) lm = gm[g];

        #pragma unroll 1
        for (int k = 0; k < BEAM; ++k) {
            unsigned up = (unsigned)(lm >> 32);
            unsigned um = __reduce_max_sync(FULL, up);
            bool hit = (up == um);
            unsigned bal = __ballot_sync(FULL, hit);
            if (__popc(bal) > 1) {               // exact value tie across lanes
                unsigned lo = hit ? (unsigned)lm : 0u;
                unsigned lw = __reduce_max_sync(FULL, lo);
                bal = __ballot_sync(FULL, hit && ((unsigned)lm == lw));
            }
            int wl = __ffs((int)bal) - 1;
            if (lane == wl) {
                u64 wkey = lm;
                seli[k] = 2047 - (int)(unsigned)wkey;
                selv[k] = ord2f((unsigned)(wkey >> 32));
                #pragma unroll
                for (int g = 0; g < 6; ++g) {
                    if (gm[g] == wkey) {
                        int base = g * 6;
                        u64 mxk = 0ull;
                        #pragma unroll
                        for (int r = 0; r < 6; ++r) {
                            int idx = base + r;
                            if (idx < 33) {
                                if (kk[idx] == wkey) kk[idx] = 0ull;
                                else if (kk[idx] > mxk) mxk = kk[idx];
                            }
                        }
                        gm[g] = mxk;
                    }
                }
                u64 nl = gm[0];
                #pragma unroll
                for (int g = 1; g < 6; ++g) if (gm[g] > nl) nl = gm[g];
                lm = nl;
            }
            __syncwarp();
        }

        // ==== phase D: commit new beam state =================================
        float npb = 0.f, npnb = 0.f; u64 nh = 0ull, npp = 0ull;
        int nlen = 0, nlast = 0, ncur = 0, nodeval = 0, nact = 0;
        bool isext = false;
        if (lane < BEAM) {
            int idx = seli[lane]; float val = selv[lane];
            bool st = idx < BEAM;
            int parent = st ? idx : ((idx - BEAM) >> 6);
            int cnew   = st ? 0   : ((idx - BEAM) & 63);
            npb  = st ? stay_pb[parent]  : NEGV;
            npnb = st ? stay_pnb[parent] : val;
            u64 hp = hcomb[parent];
            unsigned ph1 = (unsigned)(hp >> 32), ph2 = (unsigned)hp;
            unsigned cc1 = (unsigned)cnew + 1u;
            nh  = st ? hp : (((u64)(ph1 * 1000003u + cc1) << 32) | (ph2 * 69069u + cc1));
            npp = st ? pphash[parent] : hp;
            nlen  = lens[parent] + (st ? 0 : 1);
            nlast = st ? lastc[parent] : cnew;
            int pcur = curn[parent];
            ncur  = st ? pcur : (t * BEAM + lane);
            isext = !st;
            nodeval = ((pcur + 1) << 6) | cnew;
            nact = (val > -5e8f) ? 1 : 0;
        }
        __syncwarp();
        if (lane < BEAM) {
            p_b[lane] = npb; p_nb[lane] = npnb; tot[lane] = laexp(npb, npnb);
            hcomb[lane] = nh; pphash[lane] = npp;
            lens[lane] = nlen; lastc[lane] = nlast; curn[lane] = ncur;
            if (isext) nodes[t * BEAM + lane] = nodeval;
        }
        actm = __ballot_sync(FULL, nact) & 0xffffu;
        __syncwarp();
    }

    // ==== final top-4 + outputs ==============================================
    for (int e = lane; e < TOPK * TT; e += 32)
        out[2 * BB * TOPK + b * TOPK * TT + e] = -1.0f;
    __syncwarp();

    if (lane == 0) {
        unsigned used = 0u;
        for (int k = 0; k < TOPK; ++k) {
            float bv = -FLT_MAX; int bi = 0;
            for (int i = 0; i < BEAM; ++i) {
                if ((used >> i) & 1u) continue;
                if (tot[i] > bv) { bv = tot[i]; bi = i; }   // stable ties
            }
            used |= 1u << bi;
            order_s[k] = bi;
            out[b * TOPK + k]             = -bv;
            out[BB * TOPK + b * TOPK + k] = (float)lens[bi];
        }
    }
    __syncwarp();

    if (lane < TOPK) {
        int bm = order_s[lane];
        int id = curn[bm];
        float* lbl = out + 2 * BB * TOPK + (b * TOPK + lane) * TT;
        for (int pos = lens[bm] - 1; pos >= 0; --pos) {
            int pk = nodes[id];
            lbl[pos] = (float)(pk & 63);
            id = (pk >> 6) - 1;
        }
    }
}

extern "C" void kernel_launch(void* const* d_in, const int* in_sizes, int n_in,
                              void* d_out, int out_size)
{
    const float* data = (const float*)d_in[0];
    const int*   dlen = (const int*)d_in[1];
    float*       out  = (float*)d_out;

    logsoftmax_kernel<<<(TT * BB) / 8, 256>>>(data);
    ctc_beam_kernel<<<BB, 32>>>(dlen, out);
}